// round 8
// baseline (speedup 1.0000x reference)
#include <cuda_runtime.h>

#define Bb 4
#define Cc 64
#define Hh 256
#define Ww 256
#define Nn (Hh*Ww)
#define NWORDS (Nn/4)          // 16384 packed words per image
#define NG (Ww/4)              // 64 word-groups per row
#define NPAIRS 12
#define HALF_S 512
#define MAXS 1024
#define NFEAT (NPAIRS*Cc*MAXS)

#define NBLK 132
#define NTHR 1024

__device__ unsigned char g_pred[Bb*Nn];   // packed argmax bytes
__device__ unsigned char g_code[Bb*Nn];   // lab | (pd<<4)
__device__ int g_idx[NPAIRS*MAXS];

// sense-reversing grid barrier (monotonic generation, safe across replays)
__device__ unsigned g_count[4];
__device__ unsigned g_gen[4];

__device__ __forceinline__ void grid_barrier(int i) {
    __syncthreads();
    if (threadIdx.x == 0) {
        __threadfence();
        unsigned gen = ((volatile unsigned*)g_gen)[i];
        unsigned t = atomicAdd(&g_count[i], 1u);
        if (t == NBLK - 1) {
            ((volatile unsigned*)g_count)[i] = 0;
            __threadfence();
            atomicAdd(&g_gen[i], 1u);
        } else {
            while (((volatile unsigned*)g_gen)[i] == gen) { __nanosleep(64); }
            __threadfence();
        }
    }
    __syncthreads();
}

__global__ void __launch_bounds__(NTHR, 1)
k_fused(const float* __restrict__ feat,
        const int* __restrict__ labels,
        const float* __restrict__ preds,
        float* __restrict__ out) {
    int tid = threadIdx.x;
    int gt0 = blockIdx.x * NTHR + tid;

    // ---------------- phase A1: argmax (4 px/thread) -> g_pred ----------------
    for (int gt = gt0; gt < Bb*NWORDS; gt += NBLK*NTHR) {
        int b = gt >> 14;           // / NWORDS
        int w = gt & (NWORDS-1);
        const float* pb = preds + (size_t)b * 4 * Nn;
        float4 v0 = ((const float4*)pb)[w];
        float4 v1 = ((const float4*)(pb + Nn))[w];
        float4 v2 = ((const float4*)(pb + 2*Nn))[w];
        float4 v3 = ((const float4*)(pb + 3*Nn))[w];
        unsigned packed = 0;
        {   float a=v0.x; int bi=0;
            if (v1.x>a){a=v1.x;bi=1;} if (v2.x>a){a=v2.x;bi=2;} if (v3.x>a){a=v3.x;bi=3;}
            packed |= (unsigned)bi; }
        {   float a=v0.y; int bi=0;
            if (v1.y>a){a=v1.y;bi=1;} if (v2.y>a){a=v2.y;bi=2;} if (v3.y>a){a=v3.y;bi=3;}
            packed |= (unsigned)bi << 8; }
        {   float a=v0.z; int bi=0;
            if (v1.z>a){a=v1.z;bi=1;} if (v2.z>a){a=v2.z;bi=2;} if (v3.z>a){a=v3.z;bi=3;}
            packed |= (unsigned)bi << 16; }
        {   float a=v0.w; int bi=0;
            if (v1.w>a){a=v1.w;bi=1;} if (v2.w>a){a=v2.w;bi=2;} if (v3.w>a){a=v3.w;bi=3;}
            packed |= (unsigned)bi << 24; }
        ((unsigned*)g_pred)[gt] = packed;
    }
    grid_barrier(0);

    // -------- phase A2: 3x3 SIMD dilate + pack labels -> g_code ---------------
    for (int gt = gt0; gt < Bb*NWORDS; gt += NBLK*NTHR) {
        int b = gt >> 14;
        int w = gt & (NWORDS-1);
        int y = w >> 6;             // row
        int cg = w & (NG-1);        // word within row
        const unsigned* pw = (const unsigned*)g_pred + b*NWORDS;
        unsigned m = 0;
#pragma unroll
        for (int d = -1; d <= 1; d++) {
            int yy = y + d;
            if (yy < 0 || yy >= Hh) continue;
            int rb0 = yy*NG;
            unsigned wd = pw[rb0 + cg];
            unsigned lb = (cg > 0)    ? (pw[rb0 + cg - 1] >> 24)  : 0u;
            unsigned rb = (cg < NG-1) ? (pw[rb0 + cg + 1] & 0xffu) : 0u;
            unsigned wl = (wd << 8) | lb;
            unsigned wr = (wd >> 8) | (rb << 24);
            m = __vmaxu4(m, __vmaxu4(wd, __vmaxu4(wl, wr)));
        }
        int4 l = ((const int4*)(labels + (size_t)b*Nn))[w];
        unsigned lab4 = (unsigned)l.x | ((unsigned)l.y << 8) |
                        ((unsigned)l.z << 16) | ((unsigned)l.w << 24);
        ((unsigned*)g_code)[gt] = lab4 | (m << 4);
    }
    grid_barrier(1);

    // ---------------- phase B: select (blocks 0..11) --------------------------
    if (blockIdx.x < NPAIRS) {
        int pair = blockIdx.x;
        int b = pair / 3;
        int cls = pair % 3 + 1;
        g_idx[pair*MAXS + tid] = -1;
        if (tid == 0) out[NFEAT + pair] = (float)cls;

        const uint4* codes = (const uint4*)(g_code + b*Nn) + tid*4;
        uint4 q0 = codes[0], q1 = codes[1], q2 = codes[2], q3 = codes[3];
        unsigned w[16] = { q0.x,q0.y,q0.z,q0.w, q1.x,q1.y,q1.z,q1.w,
                           q2.x,q2.y,q2.z,q2.w, q3.x,q3.y,q3.z,q3.w };
        const unsigned clsL = (unsigned)cls * 0x01010101u;
        const unsigned clsH = (unsigned)cls * 0x10101010u;

        int hbits = 0, ebits = 0;
#pragma unroll
        for (int i = 0; i < 16; i++) {
            unsigned labm = __vcmpeq4(w[i] & 0x0F0F0F0Fu, clsL);
            unsigned pdm  = __vcmpeq4(w[i] & 0xF0F0F0F0u, clsH);
            ebits += __popc(labm & pdm);
            hbits += __popc(labm & ~pdm);
        }
        unsigned long long v = ((unsigned long long)(hbits>>3) << 32) | (unsigned)(ebits>>3);
        unsigned long long own = v;
        int lane = tid & 31, wid = tid >> 5;
#pragma unroll
        for (int o = 1; o < 32; o <<= 1) {
            unsigned long long n = __shfl_up_sync(0xffffffffu, v, o);
            if (lane >= o) v += n;
        }
        __shared__ unsigned long long wsum[32];
        __shared__ unsigned long long s_total;
        if (lane == 31) wsum[wid] = v;
        __syncthreads();
        if (wid == 0) {
            unsigned long long ww = wsum[lane];
#pragma unroll
            for (int o = 1; o < 32; o <<= 1) {
                unsigned long long n = __shfl_up_sync(0xffffffffu, ww, o);
                if (lane >= o) ww += n;
            }
            wsum[lane] = ww;
            if (lane == 31) s_total = ww;
        }
        __syncthreads();

        unsigned long long excl = v - own + (wid > 0 ? wsum[wid-1] : 0ULL);
        int hr = (int)(excl >> 32);
        int er = (int)(excl & 0xffffffffULL);
        int totH = (int)(s_total >> 32);
        int excess = totH > HALF_S ? totH - HALF_S : 0;

        int base = tid * 64;
        int* slots = g_idx + pair*MAXS;
#pragma unroll
        for (int i = 0; i < 16; i++) {
            unsigned labm = __vcmpeq4(w[i] & 0x0F0F0F0Fu, clsL);
            if (!labm) continue;
            unsigned pdm = __vcmpeq4(w[i] & 0xF0F0F0F0u, clsH);
#pragma unroll
            for (int k = 0; k < 4; k++) {
                if ((labm >> (k*8)) & 0xffu) {
                    int p = base + i*4 + k;
                    if ((pdm >> (k*8)) & 0xffu) {
                        int slot = HALF_S + excess + er;
                        if (slot < MAXS) slots[slot] = p;
                        er++;
                    } else {
                        if (hr < MAXS) slots[hr] = p;
                        hr++;
                    }
                }
            }
        }
    }
    grid_barrier(2);

    // ---------------- phase C: gather (grid-stride, float4) -------------------
    for (int t = gt0; t < NFEAT/4; t += NBLK*NTHR) {
        int s4   = t & 255;
        int c    = (t >> 8) & (Cc - 1);
        int pair = t >> 14;
        int b = pair / 3;
        const int* slots = g_idx + pair*MAXS + s4*4;
        const float* plane = feat + ((size_t)(b*Cc + c)) * Nn;
        int p0 = slots[0], p1 = slots[1], p2 = slots[2], p3 = slots[3];
        float4 r;
        r.x = (p0 >= 0) ? __ldg(plane + p0) : 0.0f;
        r.y = (p1 >= 0) ? __ldg(plane + p1) : 0.0f;
        r.z = (p2 >= 0) ? __ldg(plane + p2) : 0.0f;
        r.w = (p3 >= 0) ? __ldg(plane + p3) : 0.0f;
        ((float4*)out)[t] = r;
    }
}

extern "C" void kernel_launch(void* const* d_in, const int* in_sizes, int n_in,
                              void* d_out, int out_size) {
    const float* feat   = (const float*)d_in[0];  // [4,64,256,256]
    const int*   labels = (const int*)d_in[1];    // [4,256,256]
    const float* preds  = (const float*)d_in[2];  // [4,4,256,256]
    float* out = (float*)d_out;

    k_fused<<<NBLK, NTHR>>>(feat, labels, preds, out);
}